// round 16
// baseline (speedup 1.0000x reference)
#include <cuda_runtime.h>
#include <math.h>
#include <stdint.h>

#define BATCH 64
#define NOBJ  16
#define NCLS  7
#define HWDIM 108
#define H1    52
#define OC1   32
#define H2    24
#define OC2   64
#define NFC   36864      // OC2 * H2 * H2
#define NJ    512
#define NSPLIT 32
#define EPSV  1e-5f

#define C1_CTAS (13 * 64)   // 832
#define C2_CTAS (8 * 64)    // 512

// conv2 smem: xs 2 planes x 8464 + smW 11520 + sc/sh 64
#define C2_PLANE 8464       // mod 32 == 16
#define C2_ICST  264        // mod 32 == 8
#define C2_SMEM_FLOATS (2 * C2_PLANE + 11520 + 64)
#define C2_SMEM_BYTES  (C2_SMEM_FLOATS * 4)
#define C1_SMEM_FLOATS (8 * 11 * 116 + 25 * 288)   // 10208 + 7200 = 17408
#define C1_SMEM_BYTES  (C1_SMEM_FLOATS * 4)        // 69632

typedef unsigned long long u64;

// mma.sync m16n8k8 tf32 (HMMA; works on plain sm_103 target)
__device__ __forceinline__ void mma_tf32(float& c0, float& c1, float& c2, float& c3,
                                         uint32_t a0, uint32_t a1, uint32_t a2, uint32_t a3,
                                         uint32_t b0, uint32_t b1) {
    asm volatile(
        "mma.sync.aligned.m16n8k8.row.col.f32.tf32.tf32.f32 "
        "{%0,%1,%2,%3}, {%4,%5,%6,%7}, {%8,%9}, {%0,%1,%2,%3};"
        : "+f"(c0), "+f"(c1), "+f"(c2), "+f"(c3)
        : "r"(a0), "r"(a1), "r"(a2), "r"(a3), "r"(b0), "r"(b1));
}

// ---------------- scratch (device globals; no allocation) ----------------
__device__ float g_layout[BATCH * NCLS * HWDIM * HWDIM];
__device__ float g_conv1 [BATCH * OC1 * H1 * H1];
__device__ float g_conv2 [BATCH * OC2 * H2 * H2];
__device__ float g_part  [NSPLIT * BATCH * NJ];
__device__ float g_ybuf  [BATCH * NJ];
__device__ float g_s1pp[OC1][C1_CTAS], g_q1pp[OC1][C1_CTAS];
__device__ float g_s2pp[OC2][C2_CTAS], g_q2pp[OC2][C2_CTAS];
__device__ float g_s1f[OC1], g_q1f[OC1];
__device__ float g_s2f[OC2], g_q2f[OC2];
__device__ float g_w2t[OC1 * 25 * OC2];    // [ic*25+tap][oc]

// ---------------- K1: layout_bbox v3 + fused w2 transpose ----------------
__global__ void __launch_bounds__(256) k_layout(const float* __restrict__ image,
                                                const float* __restrict__ w2) {
    __shared__ float sx1[NOBJ], sx2[NOBJ], sy1[NOBJ], sy2[NOBJ];
    __shared__ float scls[NOBJ][NCLS];
    __shared__ float xmv[NOBJ][HWDIM], xbv[NOBJ][HWDIM];
    __shared__ float ymv[NOBJ][28], ybv[NOBJ][28];
    const int b   = blockIdx.y;
    const int hh0 = blockIdx.x * 27;
    const int t   = threadIdx.x;

    {
        int gi = (b * 4 + blockIdx.x) * 256 + t;
        if (gi < OC1 * 25 * OC2) {
            int kic = gi / OC2, oc = gi % OC2;
            g_w2t[gi] = w2[oc * 800 + kic];
        }
    }

    if (t < NOBJ) {
        const float* p = image + (b * NOBJ + t) * (4 + NCLS);
        float xc = p[0] * 108.f, yc = p[1] * 108.f;
        float w  = p[2] * 108.f, h  = p[3] * 108.f;
        sx1[t] = xc - 0.5f * w; sx2[t] = xc + 0.5f * w;
        sy1[t] = yc - 0.5f * h; sy2[t] = yc + 0.5f * h;
        #pragma unroll
        for (int c = 0; c < NCLS; c++) scls[t][c] = p[4 + c];
    }
    __syncthreads();

    for (int i = t; i < NOBJ * HWDIM; i += 256) {
        int o = i / HWDIM, ww = i % HWDIM;
        float xt = (float)ww;
        float x1d = xt - sx1[o], x2d = sx2[o] - xt;
        float xband = fminf(fmaxf(x1d, 0.f), 1.f) * fminf(fmaxf(x2d, 0.f), 1.f);
        float rx1 = fmaxf(1.f - fabsf(x1d), 0.f);
        float rx2 = fmaxf(1.f - fabsf(x2d), 0.f);
        xmv[o][ww] = fmaxf(rx1, rx2);
        xbv[o][ww] = xband;
    }
    for (int i = t; i < NOBJ * 27; i += 256) {
        int o = i / 27, r = i % 27;
        float yt = (float)(hh0 + r);
        float y1d = yt - sy1[o], y2d = sy2[o] - yt;
        float yband = fminf(fmaxf(y1d, 0.f), 1.f) * fminf(fmaxf(y2d, 0.f), 1.f);
        float ry1 = fmaxf(1.f - fabsf(y1d), 0.f);
        float ry2 = fmaxf(1.f - fabsf(y2d), 0.f);
        ymv[o][r] = fmaxf(ry1, ry2);
        ybv[o][r] = yband;
    }
    __syncthreads();

    for (int i = t; i < 27 * HWDIM; i += 256) {
        const int r = i / HWDIM, ww = i % HWDIM;
        const int hh = hh0 + r;
        float acc[NCLS];
        #pragma unroll
        for (int c = 0; c < NCLS; c++) acc[c] = -1e30f;
        #pragma unroll
        for (int o = 0; o < NOBJ; o++) {
            float m = fmaxf(xmv[o][ww] * ybv[o][r], ymv[o][r] * xbv[o][ww]);
            #pragma unroll
            for (int c = 0; c < NCLS; c++) acc[c] = fmaxf(acc[c], m * scls[o][c]);
        }
        #pragma unroll
        for (int c = 0; c < NCLS; c++)
            g_layout[((b * NCLS + c) * HWDIM + hh) * HWDIM + ww] = acc[c];
    }
}

// ---------------- K2: conv1 via tap-decomposed MMA + fused BN-stat partials ----------------
__global__ void __launch_bounds__(256) k_conv1_mma(const float* __restrict__ w1,
                                                   const float* __restrict__ bias) {
    extern __shared__ float sm1[];
    float* xs  = sm1;           // [ic8][11][116], ic stride 1276
    float* smW = sm1 + 10208;   // [tap25][oc*9+ic], tap stride 288
    __shared__ float redS[8][8][2], redQ[8][8][2];

    const int oh0 = blockIdx.x * 4;
    const int b   = blockIdx.y;
    const int t   = threadIdx.x;
    const int wid = t >> 5, lane = t & 31;
    const int qrow = lane >> 2, qk = lane & 3;
    const int m0 = (wid & 1) * 16;
    const int nh = wid >> 1;

    for (int i = t; i < 8 * 11 * 116; i += 256) {
        int ic = i / 1276, rem = i % 1276;
        int r = rem / 116, col = rem % 116;
        float v = 0.f;
        if (ic < 7 && col < HWDIM) {
            int row = 2 * oh0 + r;
            v = g_layout[((b * NCLS + ic) * HWDIM + row) * HWDIM + col];
        }
        xs[i] = v;
    }
    for (int i = t; i < 25 * 288; i += 256) {
        int tap = i / 288, rem = i % 288;
        int oc = rem / 9, ic = rem % 9;
        smW[i] = (ic < 7) ? w1[oc * 175 + ic * 25 + tap] : 0.f;
    }
    __syncthreads();

    float c[7][4];
    #pragma unroll
    for (int i = 0; i < 7; i++)
        #pragma unroll
        for (int j = 0; j < 4; j++) c[i][j] = 0.f;

    #pragma unroll
    for (int ky = 0; ky < 5; ky++) {
        #pragma unroll
        for (int kx = 0; kx < 5; kx++) {
            const int tap = ky * 5 + kx;
            const float* wb = &smW[tap * 288 + (m0 + qrow) * 9 + qk];
            uint32_t a0 = __float_as_uint(wb[0]);
            uint32_t a1 = __float_as_uint(wb[8 * 9]);
            uint32_t a2 = __float_as_uint(wb[4]);
            uint32_t a3 = __float_as_uint(wb[8 * 9 + 4]);
            const float* xb = &xs[qk * 1276 + (2 * nh + ky) * 116 + kx + 2 * qrow];
            #pragma unroll
            for (int i2 = 0; i2 < 7; i2++) {
                uint32_t b0 = __float_as_uint(xb[i2 * 16]);
                uint32_t b1 = __float_as_uint(xb[i2 * 16 + 4 * 1276]);
                mma_tf32(c[i2][0], c[i2][1], c[i2][2], c[i2][3], a0, a1, a2, a3, b0, b1);
            }
        }
    }

    const int oc = m0 + qrow;
    const float ba = bias[oc], bb = bias[oc + 8];
    const int orow = oh0 + nh;
    float s0 = 0.f, q0 = 0.f, s1 = 0.f, q1 = 0.f;
    #pragma unroll
    for (int i2 = 0; i2 < 7; i2++) {
        const int ow = i2 * 8 + 2 * qk;
        if (ow < H1) {
            float v0 = c[i2][0] + ba, v1 = c[i2][1] + ba;
            float v2 = c[i2][2] + bb, v3 = c[i2][3] + bb;
            float* d0 = &g_conv1[((b * OC1 + oc)     * H1 + orow) * H1 + ow];
            float* d1 = &g_conv1[((b * OC1 + oc + 8) * H1 + orow) * H1 + ow];
            d0[0] = v0; d0[1] = v1;
            d1[0] = v2; d1[1] = v3;
            s0 += v0 + v1; q0 += v0 * v0 + v1 * v1;
            s1 += v2 + v3; q1 += v2 * v2 + v3 * v3;
        }
    }
    s0 += __shfl_xor_sync(~0u, s0, 1); s0 += __shfl_xor_sync(~0u, s0, 2);
    q0 += __shfl_xor_sync(~0u, q0, 1); q0 += __shfl_xor_sync(~0u, q0, 2);
    s1 += __shfl_xor_sync(~0u, s1, 1); s1 += __shfl_xor_sync(~0u, s1, 2);
    q1 += __shfl_xor_sync(~0u, q1, 1); q1 += __shfl_xor_sync(~0u, q1, 2);
    if (qk == 0) {
        redS[wid][qrow][0] = s0; redQ[wid][qrow][0] = q0;
        redS[wid][qrow][1] = s1; redQ[wid][qrow][1] = q1;
    }
    __syncthreads();
    if (t < OC1) {
        const int mslot = t >> 4, rem = t & 15;
        const int pair = rem >> 3, qr = rem & 7;
        float S = 0.f, Q = 0.f;
        #pragma unroll
        for (int n = 0; n < 4; n++) {
            S += redS[n * 2 + mslot][qr][pair];
            Q += redQ[n * 2 + mslot][qr][pair];
        }
        const int cta = blockIdx.y * 13 + blockIdx.x;
        g_s1pp[t][cta] = S; g_q1pp[t][cta] = Q;
    }
}

// ---------------- stage-2 reducers (tiny) ----------------
__global__ void k_red1b() {
    const int c = blockIdx.x, t = threadIdx.x;
    float s = 0.f, q = 0.f;
    for (int i = t; i < C1_CTAS; i += 256) { s += g_s1pp[c][i]; q += g_q1pp[c][i]; }
    __shared__ float rs[256], rq[256];
    rs[t] = s; rq[t] = q;
    __syncthreads();
    for (int off = 128; off > 0; off >>= 1) {
        if (t < off) { rs[t] += rs[t + off]; rq[t] += rq[t + off]; }
        __syncthreads();
    }
    if (t == 0) { g_s1f[c] = rs[0]; g_q1f[c] = rq[0]; }
}
__global__ void k_red2b() {
    const int c = blockIdx.x, t = threadIdx.x;
    float s = 0.f, q = 0.f;
    for (int i = t; i < C2_CTAS; i += 256) { s += g_s2pp[c][i]; q += g_q2pp[c][i]; }
    __shared__ float rs[256], rq[256];
    rs[t] = s; rq[t] = q;
    __syncthreads();
    for (int off = 128; off > 0; off >>= 1) {
        if (t < off) { rs[t] += rs[t + off]; rq[t] += rq[t + off]; }
        __syncthreads();
    }
    if (t == 0) { g_s2f[c] = rs[0]; g_q2f[c] = rq[0]; }
}

// ---------------- K4: conv2 MMA, even/odd-plane xs (conflict-free b-loads) ----------------
// xs[plane][ic][9 rows][28 cols]; plane stride 8464 (mod32=16), ic stride 264 (mod32=8).
__global__ void __launch_bounds__(256) k_conv2_mma(const float* __restrict__ bias,
                        const float* __restrict__ g1, const float* __restrict__ b1) {
    extern __shared__ float sm[];
    float* xs  = sm;                          // 2 * 8464 floats
    float* smW = sm + 2 * C2_PLANE;           // 11520 floats
    float* sc1 = smW + 11520;                 // 32
    float* sh1 = sc1 + 32;                    // 32
    __shared__ float redS[8][8][2], redQ[8][8][2];

    const int oh0 = blockIdx.x * 3;
    const int b   = blockIdx.y;
    const int t   = threadIdx.x;
    const int wid = t >> 5, lane = t & 31;
    const int qrow = lane >> 2, qk = lane & 3;
    const int m0 = (wid & 3) * 16;
    const int nh = wid >> 2;
    const int NT = nh ? 4 : 5;

    if (t < OC1) {
        float s = g_s1f[t], q = g_q1f[t];
        float n = (float)(BATCH * H1 * H1);
        float m = s / n;
        float v = q / n - m * m;
        float sc = rsqrtf(v + EPSV) * g1[t];
        sc1[t] = sc; sh1[t] = b1[t] - m * sc;
    }
    __syncthreads();

    // stage X with plane split: col -> (plane = col&1, cc = col>>1)
    for (int i = t; i < 32 * 9 * 52; i += 256) {
        int ic = i / 468, rem = i % 468;
        int r = rem / 52, col = rem % 52;
        float v = g_conv1[((b * OC1 + ic) * H1 + 2 * oh0 + r) * H1 + col];
        v = v * sc1[ic] + sh1[ic];
        v = v > 0.f ? v : 0.2f * v;
        xs[(col & 1) * C2_PLANE + ic * C2_ICST + r * 28 + (col >> 1)] = v;
    }

    float c[5][4];
    #pragma unroll
    for (int i = 0; i < 5; i++)
        #pragma unroll
        for (int j = 0; j < 4; j++) c[i][j] = 0.f;

    // per-tile offset: 56*rowi + owb (rows are 2*rowi(+ky), row stride 28)
    int toff[5];
    #pragma unroll
    for (int i2 = 0; i2 < 5; i2++) {
        int n0 = nh * 40 + i2 * 8;
        toff[i2] = (n0 / 24) * 56 + (n0 % 24);
    }

    for (int ky = 0; ky < 5; ky++) {
        __syncthreads();
        for (int i = t; i < 5 * 32 * 64; i += 256) {
            int oc = i & 63, q = i >> 6;
            int kx = q >> 5, ic = q & 31;
            smW[kx * 2304 + ic * 72 + oc] = g_w2t[(ic * 25 + ky * 5 + kx) * OC2 + oc];
        }
        __syncthreads();
        #pragma unroll
        for (int kx = 0; kx < 5; kx++) {
            const float* xplane = xs + (kx & 1) * C2_PLANE + (kx >> 1) + ky * 28 + qrow;
            #pragma unroll
            for (int ks = 0; ks < 4; ks++) {
                const float* wb = &smW[kx * 2304 + (ks * 8 + qk) * 72 + m0 + qrow];
                uint32_t a0 = __float_as_uint(wb[0]);
                uint32_t a1 = __float_as_uint(wb[8]);
                uint32_t a2 = __float_as_uint(wb[4 * 72]);
                uint32_t a3 = __float_as_uint(wb[4 * 72 + 8]);
                const float* xb = xplane + (ks * 8 + qk) * C2_ICST;
                for (int i2 = 0; i2 < NT; i2++) {
                    uint32_t b0 = __float_as_uint(xb[toff[i2]]);
                    uint32_t b1 = __float_as_uint(xb[toff[i2] + 4 * C2_ICST]);
                    mma_tf32(c[i2][0], c[i2][1], c[i2][2], c[i2][3], a0, a1, a2, a3, b0, b1);
                }
            }
        }
    }

    const int oc = m0 + qrow;
    const float ba = bias[oc], bb = bias[oc + 8];
    float s0 = 0.f, q0 = 0.f, s1 = 0.f, q1 = 0.f;
    for (int i2 = 0; i2 < NT; i2++) {
        const int n0 = nh * 40 + i2 * 8;
        const int pos = (oh0 + n0 / 24) * 24 + (n0 % 24) + 2 * qk;
        float v0 = c[i2][0] + ba, v1 = c[i2][1] + ba;
        float v2 = c[i2][2] + bb, v3 = c[i2][3] + bb;
        float* d0 = &g_conv2[(b * OC2 + oc) * 576 + pos];
        float* d1 = &g_conv2[(b * OC2 + oc + 8) * 576 + pos];
        d0[0] = v0; d0[1] = v1;
        d1[0] = v2; d1[1] = v3;
        s0 += v0 + v1; q0 += v0 * v0 + v1 * v1;
        s1 += v2 + v3; q1 += v2 * v2 + v3 * v3;
    }
    s0 += __shfl_xor_sync(~0u, s0, 1); s0 += __shfl_xor_sync(~0u, s0, 2);
    q0 += __shfl_xor_sync(~0u, q0, 1); q0 += __shfl_xor_sync(~0u, q0, 2);
    s1 += __shfl_xor_sync(~0u, s1, 1); s1 += __shfl_xor_sync(~0u, s1, 2);
    q1 += __shfl_xor_sync(~0u, q1, 1); q1 += __shfl_xor_sync(~0u, q1, 2);
    if (qk == 0) {
        redS[wid][qrow][0] = s0; redQ[wid][qrow][0] = q0;
        redS[wid][qrow][1] = s1; redQ[wid][qrow][1] = q1;
    }
    __syncthreads();
    if (t < OC2) {
        const int mslot = t >> 4, rem = t & 15;
        const int pair = rem >> 3, qr = rem & 7;
        float S = 0.f, Q = 0.f;
        #pragma unroll
        for (int n = 0; n < 2; n++) {
            S += redS[n * 4 + mslot][qr][pair];
            Q += redQ[n * 4 + mslot][qr][pair];
        }
        const int cta = blockIdx.y * 8 + blockIdx.x;
        g_s2pp[t][cta] = S; g_q2pp[t][cta] = Q;
    }
}

// ---------------- K6: fc1 via mma.sync tf32 ----------------
__global__ void __launch_bounds__(256) k_fc1_mma(const float* __restrict__ w,
                      const float* __restrict__ g2, const float* __restrict__ b2) {
    __shared__ float smA[64 * 36];
    __shared__ float smB[64 * 36];
    const int jb = blockIdx.x, sp = blockIdx.y;
    const int t = threadIdx.x;
    const int wid = t >> 5, lane = t & 31;
    const int qrow = lane >> 2, qk = lane & 3;
    const int j0 = (wid & 3) * 16;
    const int b0 = (wid >> 2) * 32;

    const int c0 = 2 * sp;
    float scv[2], shv[2];
    #pragma unroll
    for (int ci = 0; ci < 2; ci++) {
        float s = g_s2f[c0 + ci], q = g_q2f[c0 + ci];
        float n = (float)(BATCH * H2 * H2);
        float m = s / n;
        float var = q / n - m * m;
        float sc = rsqrtf(var + EPSV) * g2[c0 + ci];
        scv[ci] = sc; shv[ci] = b2[c0 + ci] - m * sc;
    }

    float c[4][4];
    #pragma unroll
    for (int nt = 0; nt < 4; nt++)
        #pragma unroll
        for (int i = 0; i < 4; i++) c[nt][i] = 0.f;

    const int kbase = sp * 1152;
    for (int ch = 0; ch < 36; ch++) {
        const int k0 = kbase + ch * 32;
        const float sc = scv[ch >= 18], sh = shv[ch >= 18];
        __syncthreads();
        #pragma unroll
        for (int rep = 0; rep < 2; rep++) {
            int idx = rep * 256 + t;
            int row = idx >> 3, kq = idx & 7;
            float4 v = *(const float4*)&w[(jb * 64 + row) * NFC + k0 + kq * 4];
            float* dst = &smA[row * 36 + kq * 4];
            dst[0] = v.x; dst[1] = v.y; dst[2] = v.z; dst[3] = v.w;
        }
        #pragma unroll
        for (int rep = 0; rep < 2; rep++) {
            int idx = rep * 256 + t;
            int row = idx >> 3, kq = idx & 7;
            float4 v = *(const float4*)&g_conv2[row * NFC + k0 + kq * 4];
            v.x = v.x * sc + sh; v.x = v.x > 0.f ? v.x : 0.2f * v.x;
            v.y = v.y * sc + sh; v.y = v.y > 0.f ? v.y : 0.2f * v.y;
            v.z = v.z * sc + sh; v.z = v.z > 0.f ? v.z : 0.2f * v.z;
            v.w = v.w * sc + sh; v.w = v.w > 0.f ? v.w : 0.2f * v.w;
            float* dst = &smB[row * 36 + kq * 4];
            dst[0] = v.x; dst[1] = v.y; dst[2] = v.z; dst[3] = v.w;
        }
        __syncthreads();
        #pragma unroll
        for (int ks = 0; ks < 4; ks++) {
            const int kk = ks * 8;
            uint32_t a0 = __float_as_uint(smA[(j0 + qrow)     * 36 + kk + qk]);
            uint32_t a1 = __float_as_uint(smA[(j0 + qrow + 8) * 36 + kk + qk]);
            uint32_t a2 = __float_as_uint(smA[(j0 + qrow)     * 36 + kk + qk + 4]);
            uint32_t a3 = __float_as_uint(smA[(j0 + qrow + 8) * 36 + kk + qk + 4]);
            #pragma unroll
            for (int nt = 0; nt < 4; nt++) {
                uint32_t bb0 = __float_as_uint(smB[(b0 + nt * 8 + qrow) * 36 + kk + qk]);
                uint32_t bb1 = __float_as_uint(smB[(b0 + nt * 8 + qrow) * 36 + kk + qk + 4]);
                mma_tf32(c[nt][0], c[nt][1], c[nt][2], c[nt][3], a0, a1, a2, a3, bb0, bb1);
            }
        }
    }
    const int jg = jb * 64 + j0 + qrow;
    #pragma unroll
    for (int nt = 0; nt < 4; nt++) {
        const int bcol = b0 + nt * 8 + 2 * qk;
        g_part[(sp * BATCH + bcol)     * NJ + jg]     = c[nt][0];
        g_part[(sp * BATCH + bcol + 1) * NJ + jg]     = c[nt][1];
        g_part[(sp * BATCH + bcol)     * NJ + jg + 8] = c[nt][2];
        g_part[(sp * BATCH + bcol + 1) * NJ + jg + 8] = c[nt][3];
    }
}

// ---------------- K7: reduce split-K partials + fc1 bias ----------------
__global__ void k_redpart(const float* __restrict__ fc1b) {
    const int b = blockIdx.x, j = threadIdx.x;
    float y = fc1b[j];
    #pragma unroll
    for (int s = 0; s < NSPLIT; s++) y += g_part[(s * BATCH + b) * NJ + j];
    g_ybuf[b * NJ + j] = y;
}

// ---------------- K8: bn3 + leaky + fc2 + sigmoid ----------------
__global__ void k_final(const float* __restrict__ g3, const float* __restrict__ b3,
                        const float* __restrict__ w2, const float* __restrict__ bias2,
                        float* __restrict__ out) {
    __shared__ float sc[NJ], sh[NJ], w2s[NJ];
    const int t = threadIdx.x;
    float s = 0.f, ss = 0.f;
    for (int b = 0; b < BATCH; b++) {
        float v = g_ybuf[b * NJ + t];
        s += v; ss += v * v;
    }
    float m = s * (1.f / BATCH);
    float var = ss * (1.f / BATCH) - m * m;
    float scale = rsqrtf(var + EPSV) * g3[t];
    sc[t] = scale; sh[t] = b3[t] - m * scale; w2s[t] = w2[t];
    __syncthreads();
    const int warp = t / 32, lane = t % 32;
    for (int b = warp * 4; b < warp * 4 + 4; b++) {
        float p = 0.f;
        for (int j = lane; j < NJ; j += 32) {
            float v = g_ybuf[b * NJ + j] * sc[j] + sh[j];
            v = v > 0.f ? v : 0.2f * v;
            p += v * w2s[j];
        }
        #pragma unroll
        for (int off = 16; off > 0; off >>= 1)
            p += __shfl_down_sync(0xffffffffu, p, off);
        if (lane == 0) out[b] = 1.f / (1.f + expf(-(p + bias2[0])));
    }
}

// ---------------- launch ----------------
extern "C" void kernel_launch(void* const* d_in, const int* in_sizes, int n_in,
                              void* d_out, int out_size) {
    (void)in_sizes; (void)n_in; (void)out_size;
    const float* image = (const float*)d_in[0];
    const float* c1w = (const float*)d_in[1];
    const float* c1b = (const float*)d_in[2];
    const float* g1  = (const float*)d_in[3];
    const float* b1  = (const float*)d_in[4];
    const float* c2w = (const float*)d_in[5];
    const float* c2b = (const float*)d_in[6];
    const float* g2  = (const float*)d_in[7];
    const float* b2  = (const float*)d_in[8];
    const float* fw1 = (const float*)d_in[9];
    const float* fb1 = (const float*)d_in[10];
    const float* g3  = (const float*)d_in[11];
    const float* b3  = (const float*)d_in[12];
    const float* fw2 = (const float*)d_in[13];
    const float* fb2 = (const float*)d_in[14];
    float* out = (float*)d_out;

    cudaFuncSetAttribute(k_conv1_mma, cudaFuncAttributeMaxDynamicSharedMemorySize,
                         C1_SMEM_BYTES);
    cudaFuncSetAttribute(k_conv2_mma, cudaFuncAttributeMaxDynamicSharedMemorySize,
                         C2_SMEM_BYTES);

    k_layout    <<<dim3(4, 64), 256>>>(image, c2w);
    k_conv1_mma <<<dim3(13, 64), 256, C1_SMEM_BYTES>>>(c1w, c1b);
    k_red1b     <<<OC1, 256>>>();
    k_conv2_mma <<<dim3(8, 64), 256, C2_SMEM_BYTES>>>(c2b, g1, b1);
    k_red2b     <<<OC2, 256>>>();
    k_fc1_mma   <<<dim3(8, NSPLIT), 256>>>(fw1, g2, b2);
    k_redpart   <<<BATCH, NJ>>>(fb1);
    k_final     <<<1, NJ>>>(g3, b3, fw2, fb2, out);
}

// round 17
// speedup vs baseline: 1.1228x; 1.1228x over previous
#include <cuda_runtime.h>
#include <math.h>
#include <stdint.h>

#define BATCH 64
#define NOBJ  16
#define NCLS  7
#define HWDIM 108
#define H1    52
#define OC1   32
#define H2    24
#define OC2   64
#define NFC   36864      // OC2 * H2 * H2
#define NJ    512
#define NSPLIT 32
#define EPSV  1e-5f

#define C1_CTAS (13 * 64)   // 832

// conv2 (ic-split): xs 2 planes x 4224 + smW 5760 + sc/sh 32
#define C2_PLANE 4224       // 16 ic * 264
#define C2_ICST  264        // mod 32 == 8
#define C2_SMEM_FLOATS (2 * C2_PLANE + 5760 + 32)
#define C2_SMEM_BYTES  (C2_SMEM_FLOATS * 4)
#define C1_SMEM_FLOATS (8 * 11 * 116 + 25 * 288)   // 10208 + 7200 = 17408
#define C1_SMEM_BYTES  (C1_SMEM_FLOATS * 4)        // 69632

typedef unsigned long long u64;

// mma.sync m16n8k8 tf32 (HMMA; works on plain sm_103 target)
__device__ __forceinline__ void mma_tf32(float& c0, float& c1, float& c2, float& c3,
                                         uint32_t a0, uint32_t a1, uint32_t a2, uint32_t a3,
                                         uint32_t b0, uint32_t b1) {
    asm volatile(
        "mma.sync.aligned.m16n8k8.row.col.f32.tf32.tf32.f32 "
        "{%0,%1,%2,%3}, {%4,%5,%6,%7}, {%8,%9}, {%0,%1,%2,%3};"
        : "+f"(c0), "+f"(c1), "+f"(c2), "+f"(c3)
        : "r"(a0), "r"(a1), "r"(a2), "r"(a3), "r"(b0), "r"(b1));
}

// ---------------- scratch (device globals; no allocation) ----------------
__device__ float g_layout[BATCH * NCLS * HWDIM * HWDIM];
__device__ float g_conv1 [BATCH * OC1 * H1 * H1];
__device__ float g_conv2 [BATCH * OC2 * H2 * H2];
__device__ float g_c2a   [BATCH * OC2 * H2 * H2];   // ic-split partial 0
__device__ float g_c2b   [BATCH * OC2 * H2 * H2];   // ic-split partial 1
__device__ float g_part  [NSPLIT * BATCH * NJ];
__device__ float g_ybuf  [BATCH * NJ];
__device__ float g_s1pp[OC1][C1_CTAS], g_q1pp[OC1][C1_CTAS];
__device__ float g_s2p[8][OC2], g_q2p[8][OC2];      // merge-kernel partials
__device__ float g_s1f[OC1], g_q1f[OC1];
__device__ float g_w2t[OC1 * 25 * OC2];    // [ic*25+tap][oc]

// ---------------- K1: layout_bbox v3 + fused w2 transpose ----------------
__global__ void __launch_bounds__(256) k_layout(const float* __restrict__ image,
                                                const float* __restrict__ w2) {
    __shared__ float sx1[NOBJ], sx2[NOBJ], sy1[NOBJ], sy2[NOBJ];
    __shared__ float scls[NOBJ][NCLS];
    __shared__ float xmv[NOBJ][HWDIM], xbv[NOBJ][HWDIM];
    __shared__ float ymv[NOBJ][28], ybv[NOBJ][28];
    const int b   = blockIdx.y;
    const int hh0 = blockIdx.x * 27;
    const int t   = threadIdx.x;

    {
        int gi = (b * 4 + blockIdx.x) * 256 + t;
        if (gi < OC1 * 25 * OC2) {
            int kic = gi / OC2, oc = gi % OC2;
            g_w2t[gi] = w2[oc * 800 + kic];
        }
    }

    if (t < NOBJ) {
        const float* p = image + (b * NOBJ + t) * (4 + NCLS);
        float xc = p[0] * 108.f, yc = p[1] * 108.f;
        float w  = p[2] * 108.f, h  = p[3] * 108.f;
        sx1[t] = xc - 0.5f * w; sx2[t] = xc + 0.5f * w;
        sy1[t] = yc - 0.5f * h; sy2[t] = yc + 0.5f * h;
        #pragma unroll
        for (int c = 0; c < NCLS; c++) scls[t][c] = p[4 + c];
    }
    __syncthreads();

    for (int i = t; i < NOBJ * HWDIM; i += 256) {
        int o = i / HWDIM, ww = i % HWDIM;
        float xt = (float)ww;
        float x1d = xt - sx1[o], x2d = sx2[o] - xt;
        float xband = fminf(fmaxf(x1d, 0.f), 1.f) * fminf(fmaxf(x2d, 0.f), 1.f);
        float rx1 = fmaxf(1.f - fabsf(x1d), 0.f);
        float rx2 = fmaxf(1.f - fabsf(x2d), 0.f);
        xmv[o][ww] = fmaxf(rx1, rx2);
        xbv[o][ww] = xband;
    }
    for (int i = t; i < NOBJ * 27; i += 256) {
        int o = i / 27, r = i % 27;
        float yt = (float)(hh0 + r);
        float y1d = yt - sy1[o], y2d = sy2[o] - yt;
        float yband = fminf(fmaxf(y1d, 0.f), 1.f) * fminf(fmaxf(y2d, 0.f), 1.f);
        float ry1 = fmaxf(1.f - fabsf(y1d), 0.f);
        float ry2 = fmaxf(1.f - fabsf(y2d), 0.f);
        ymv[o][r] = fmaxf(ry1, ry2);
        ybv[o][r] = yband;
    }
    __syncthreads();

    for (int i = t; i < 27 * HWDIM; i += 256) {
        const int r = i / HWDIM, ww = i % HWDIM;
        const int hh = hh0 + r;
        float acc[NCLS];
        #pragma unroll
        for (int c = 0; c < NCLS; c++) acc[c] = -1e30f;
        #pragma unroll
        for (int o = 0; o < NOBJ; o++) {
            float m = fmaxf(xmv[o][ww] * ybv[o][r], ymv[o][r] * xbv[o][ww]);
            #pragma unroll
            for (int c = 0; c < NCLS; c++) acc[c] = fmaxf(acc[c], m * scls[o][c]);
        }
        #pragma unroll
        for (int c = 0; c < NCLS; c++)
            g_layout[((b * NCLS + c) * HWDIM + hh) * HWDIM + ww] = acc[c];
    }
}

// ---------------- K2: conv1 via tap-decomposed MMA + fused BN-stat partials ----------------
__global__ void __launch_bounds__(256) k_conv1_mma(const float* __restrict__ w1,
                                                   const float* __restrict__ bias) {
    extern __shared__ float sm1[];
    float* xs  = sm1;           // [ic8][11][116], ic stride 1276
    float* smW = sm1 + 10208;   // [tap25][oc*9+ic], tap stride 288
    __shared__ float redS[8][8][2], redQ[8][8][2];

    const int oh0 = blockIdx.x * 4;
    const int b   = blockIdx.y;
    const int t   = threadIdx.x;
    const int wid = t >> 5, lane = t & 31;
    const int qrow = lane >> 2, qk = lane & 3;
    const int m0 = (wid & 1) * 16;
    const int nh = wid >> 1;

    for (int i = t; i < 8 * 11 * 116; i += 256) {
        int ic = i / 1276, rem = i % 1276;
        int r = rem / 116, col = rem % 116;
        float v = 0.f;
        if (ic < 7 && col < HWDIM) {
            int row = 2 * oh0 + r;
            v = g_layout[((b * NCLS + ic) * HWDIM + row) * HWDIM + col];
        }
        xs[i] = v;
    }
    for (int i = t; i < 25 * 288; i += 256) {
        int tap = i / 288, rem = i % 288;
        int oc = rem / 9, ic = rem % 9;
        smW[i] = (ic < 7) ? w1[oc * 175 + ic * 25 + tap] : 0.f;
    }
    __syncthreads();

    float c[7][4];
    #pragma unroll
    for (int i = 0; i < 7; i++)
        #pragma unroll
        for (int j = 0; j < 4; j++) c[i][j] = 0.f;

    #pragma unroll
    for (int ky = 0; ky < 5; ky++) {
        #pragma unroll
        for (int kx = 0; kx < 5; kx++) {
            const int tap = ky * 5 + kx;
            const float* wb = &smW[tap * 288 + (m0 + qrow) * 9 + qk];
            uint32_t a0 = __float_as_uint(wb[0]);
            uint32_t a1 = __float_as_uint(wb[8 * 9]);
            uint32_t a2 = __float_as_uint(wb[4]);
            uint32_t a3 = __float_as_uint(wb[8 * 9 + 4]);
            const float* xb = &xs[qk * 1276 + (2 * nh + ky) * 116 + kx + 2 * qrow];
            #pragma unroll
            for (int i2 = 0; i2 < 7; i2++) {
                uint32_t b0 = __float_as_uint(xb[i2 * 16]);
                uint32_t b1 = __float_as_uint(xb[i2 * 16 + 4 * 1276]);
                mma_tf32(c[i2][0], c[i2][1], c[i2][2], c[i2][3], a0, a1, a2, a3, b0, b1);
            }
        }
    }

    const int oc = m0 + qrow;
    const float ba = bias[oc], bb = bias[oc + 8];
    const int orow = oh0 + nh;
    float s0 = 0.f, q0 = 0.f, s1 = 0.f, q1 = 0.f;
    #pragma unroll
    for (int i2 = 0; i2 < 7; i2++) {
        const int ow = i2 * 8 + 2 * qk;
        if (ow < H1) {
            float v0 = c[i2][0] + ba, v1 = c[i2][1] + ba;
            float v2 = c[i2][2] + bb, v3 = c[i2][3] + bb;
            float* d0 = &g_conv1[((b * OC1 + oc)     * H1 + orow) * H1 + ow];
            float* d1 = &g_conv1[((b * OC1 + oc + 8) * H1 + orow) * H1 + ow];
            d0[0] = v0; d0[1] = v1;
            d1[0] = v2; d1[1] = v3;
            s0 += v0 + v1; q0 += v0 * v0 + v1 * v1;
            s1 += v2 + v3; q1 += v2 * v2 + v3 * v3;
        }
    }
    s0 += __shfl_xor_sync(~0u, s0, 1); s0 += __shfl_xor_sync(~0u, s0, 2);
    q0 += __shfl_xor_sync(~0u, q0, 1); q0 += __shfl_xor_sync(~0u, q0, 2);
    s1 += __shfl_xor_sync(~0u, s1, 1); s1 += __shfl_xor_sync(~0u, s1, 2);
    q1 += __shfl_xor_sync(~0u, q1, 1); q1 += __shfl_xor_sync(~0u, q1, 2);
    if (qk == 0) {
        redS[wid][qrow][0] = s0; redQ[wid][qrow][0] = q0;
        redS[wid][qrow][1] = s1; redQ[wid][qrow][1] = q1;
    }
    __syncthreads();
    if (t < OC1) {
        const int mslot = t >> 4, rem = t & 15;
        const int pair = rem >> 3, qr = rem & 7;
        float S = 0.f, Q = 0.f;
        #pragma unroll
        for (int n = 0; n < 4; n++) {
            S += redS[n * 2 + mslot][qr][pair];
            Q += redQ[n * 2 + mslot][qr][pair];
        }
        const int cta = blockIdx.y * 13 + blockIdx.x;
        g_s1pp[t][cta] = S; g_q1pp[t][cta] = Q;
    }
}

// ---------------- stage-2 reducer for conv1 stats ----------------
__global__ void k_red1b() {
    const int c = blockIdx.x, t = threadIdx.x;
    float s = 0.f, q = 0.f;
    for (int i = t; i < C1_CTAS; i += 256) { s += g_s1pp[c][i]; q += g_q1pp[c][i]; }
    __shared__ float rs[256], rq[256];
    rs[t] = s; rq[t] = q;
    __syncthreads();
    for (int off = 128; off > 0; off >>= 1) {
        if (t < off) { rs[t] += rs[t + off]; rq[t] += rq[t + off]; }
        __syncthreads();
    }
    if (t == 0) { g_s1f[c] = rs[0]; g_q1f[c] = rq[0]; }
}

// ---------------- K4: conv2 MMA, ic-split (16 ic per CTA) ----------------
// grid (ytile 0..7, b, split 0..1). xs[plane][ic16][9][28]; partials to g_c2a/g_c2b.
__global__ void __launch_bounds__(256) k_conv2_mma(const float* __restrict__ g1,
                                                   const float* __restrict__ b1) {
    extern __shared__ float sm[];
    float* xs  = sm;                          // 2 * 4224
    float* smW = sm + 2 * C2_PLANE;           // 5760
    float* sc1 = smW + 5760;                  // 16
    float* sh1 = sc1 + 16;                    // 16

    const int oh0 = blockIdx.x * 3;
    const int b   = blockIdx.y;
    const int icb = blockIdx.z * 16;
    const int t   = threadIdx.x;
    const int wid = t >> 5, lane = t & 31;
    const int qrow = lane >> 2, qk = lane & 3;
    const int m0 = (wid & 3) * 16;
    const int nh = wid >> 2;
    const int NT = nh ? 4 : 5;

    if (t < 16) {
        const int ic = icb + t;
        float s = g_s1f[ic], q = g_q1f[ic];
        float n = (float)(BATCH * H1 * H1);
        float m = s / n;
        float v = q / n - m * m;
        float sc = rsqrtf(v + EPSV) * g1[ic];
        sc1[t] = sc; sh1[t] = b1[ic] - m * sc;
    }
    __syncthreads();

    // stage X (16 ic) with plane split
    for (int i = t; i < 16 * 9 * 52; i += 256) {
        int ic = i / 468, rem = i % 468;
        int r = rem / 52, col = rem % 52;
        float v = g_conv1[((b * OC1 + icb + ic) * H1 + 2 * oh0 + r) * H1 + col];
        v = v * sc1[ic] + sh1[ic];
        v = v > 0.f ? v : 0.2f * v;
        xs[(col & 1) * C2_PLANE + ic * C2_ICST + r * 28 + (col >> 1)] = v;
    }

    float c[5][4];
    #pragma unroll
    for (int i = 0; i < 5; i++)
        #pragma unroll
        for (int j = 0; j < 4; j++) c[i][j] = 0.f;

    int toff[5];
    #pragma unroll
    for (int i2 = 0; i2 < 5; i2++) {
        int n0 = nh * 40 + i2 * 8;
        toff[i2] = (n0 / 24) * 56 + (n0 % 24);
    }

    for (int ky = 0; ky < 5; ky++) {
        __syncthreads();
        for (int i = t; i < 5 * 16 * 64; i += 256) {   // 5120 elems, 20/thread
            int oc = i & 63, q = i >> 6;
            int kx = q >> 4, ic = q & 15;
            smW[kx * 1152 + ic * 72 + oc] = g_w2t[((icb + ic) * 25 + ky * 5 + kx) * OC2 + oc];
        }
        __syncthreads();
        #pragma unroll
        for (int kx = 0; kx < 5; kx++) {
            const float* xplane = xs + (kx & 1) * C2_PLANE + (kx >> 1) + ky * 28 + qrow;
            #pragma unroll
            for (int ks = 0; ks < 2; ks++) {
                const float* wb = &smW[kx * 1152 + (ks * 8 + qk) * 72 + m0 + qrow];
                uint32_t a0 = __float_as_uint(wb[0]);
                uint32_t a1 = __float_as_uint(wb[8]);
                uint32_t a2 = __float_as_uint(wb[4 * 72]);
                uint32_t a3 = __float_as_uint(wb[4 * 72 + 8]);
                const float* xb = xplane + (ks * 8 + qk) * C2_ICST;
                for (int i2 = 0; i2 < NT; i2++) {
                    uint32_t b0 = __float_as_uint(xb[toff[i2]]);
                    uint32_t b1 = __float_as_uint(xb[toff[i2] + 4 * C2_ICST]);
                    mma_tf32(c[i2][0], c[i2][1], c[i2][2], c[i2][3], a0, a1, a2, a3, b0, b1);
                }
            }
        }
    }

    // epilogue: raw partials (no bias, no stats)
    float* buf = blockIdx.z ? g_c2b : g_c2a;
    const int oc = m0 + qrow;
    for (int i2 = 0; i2 < NT; i2++) {
        const int n0 = nh * 40 + i2 * 8;
        const int pos = (oh0 + n0 / 24) * 24 + (n0 % 24) + 2 * qk;
        float* d0 = &buf[(b * OC2 + oc) * 576 + pos];
        float* d1 = &buf[(b * OC2 + oc + 8) * 576 + pos];
        d0[0] = c[i2][0]; d0[1] = c[i2][1];
        d1[0] = c[i2][2]; d1[1] = c[i2][3];
    }
}

// ---------------- K5: merge ic-split partials + bias, compute BN partials ----------------
// grid (c 0..63, bg 0..7), 256 threads. Deterministic.
__global__ void k_c2merge(const float* __restrict__ bias) {
    const int c = blockIdx.x, bg = blockIdx.y, t = threadIdx.x;
    const float bc = bias[c];
    float s = 0.f, ss = 0.f;
    for (int i = t; i < 8 * 144; i += 256) {
        int b = bg * 8 + i / 144;
        int idx = (b * OC2 + c) * 576 + (i % 144) * 4;
        float4 va = *(const float4*)&g_c2a[idx];
        float4 vb = *(const float4*)&g_c2b[idx];
        float4 v;
        v.x = va.x + vb.x + bc;
        v.y = va.y + vb.y + bc;
        v.z = va.z + vb.z + bc;
        v.w = va.w + vb.w + bc;
        *(float4*)&g_conv2[idx] = v;
        s  += (v.x + v.y) + (v.z + v.w);
        ss += (v.x * v.x + v.y * v.y) + (v.z * v.z + v.w * v.w);
    }
    __shared__ float rs[256], rq[256];
    rs[t] = s; rq[t] = ss;
    __syncthreads();
    for (int off = 128; off > 0; off >>= 1) {
        if (t < off) { rs[t] += rs[t + off]; rq[t] += rq[t + off]; }
        __syncthreads();
    }
    if (t == 0) { g_s2p[bg][c] = rs[0]; g_q2p[bg][c] = rq[0]; }
}

// ---------------- K6: fc1 via mma.sync tf32 (sums 8 merge partials for BN) ----------------
__global__ void __launch_bounds__(256) k_fc1_mma(const float* __restrict__ w,
                      const float* __restrict__ g2, const float* __restrict__ b2) {
    __shared__ float smA[64 * 36];
    __shared__ float smB[64 * 36];
    const int jb = blockIdx.x, sp = blockIdx.y;
    const int t = threadIdx.x;
    const int wid = t >> 5, lane = t & 31;
    const int qrow = lane >> 2, qk = lane & 3;
    const int j0 = (wid & 3) * 16;
    const int b0 = (wid >> 2) * 32;

    const int c0 = 2 * sp;
    float scv[2], shv[2];
    #pragma unroll
    for (int ci = 0; ci < 2; ci++) {
        float s = 0.f, q = 0.f;
        #pragma unroll
        for (int i = 0; i < 8; i++) { s += g_s2p[i][c0 + ci]; q += g_q2p[i][c0 + ci]; }
        float n = (float)(BATCH * H2 * H2);
        float m = s / n;
        float var = q / n - m * m;
        float sc = rsqrtf(var + EPSV) * g2[c0 + ci];
        scv[ci] = sc; shv[ci] = b2[c0 + ci] - m * sc;
    }

    float c[4][4];
    #pragma unroll
    for (int nt = 0; nt < 4; nt++)
        #pragma unroll
        for (int i = 0; i < 4; i++) c[nt][i] = 0.f;

    const int kbase = sp * 1152;
    for (int ch = 0; ch < 36; ch++) {
        const int k0 = kbase + ch * 32;
        const float sc = scv[ch >= 18], sh = shv[ch >= 18];
        __syncthreads();
        #pragma unroll
        for (int rep = 0; rep < 2; rep++) {
            int idx = rep * 256 + t;
            int row = idx >> 3, kq = idx & 7;
            float4 v = *(const float4*)&w[(jb * 64 + row) * NFC + k0 + kq * 4];
            float* dst = &smA[row * 36 + kq * 4];
            dst[0] = v.x; dst[1] = v.y; dst[2] = v.z; dst[3] = v.w;
        }
        #pragma unroll
        for (int rep = 0; rep < 2; rep++) {
            int idx = rep * 256 + t;
            int row = idx >> 3, kq = idx & 7;
            float4 v = *(const float4*)&g_conv2[row * NFC + k0 + kq * 4];
            v.x = v.x * sc + sh; v.x = v.x > 0.f ? v.x : 0.2f * v.x;
            v.y = v.y * sc + sh; v.y = v.y > 0.f ? v.y : 0.2f * v.y;
            v.z = v.z * sc + sh; v.z = v.z > 0.f ? v.z : 0.2f * v.z;
            v.w = v.w * sc + sh; v.w = v.w > 0.f ? v.w : 0.2f * v.w;
            float* dst = &smB[row * 36 + kq * 4];
            dst[0] = v.x; dst[1] = v.y; dst[2] = v.z; dst[3] = v.w;
        }
        __syncthreads();
        #pragma unroll
        for (int ks = 0; ks < 4; ks++) {
            const int kk = ks * 8;
            uint32_t a0 = __float_as_uint(smA[(j0 + qrow)     * 36 + kk + qk]);
            uint32_t a1 = __float_as_uint(smA[(j0 + qrow + 8) * 36 + kk + qk]);
            uint32_t a2 = __float_as_uint(smA[(j0 + qrow)     * 36 + kk + qk + 4]);
            uint32_t a3 = __float_as_uint(smA[(j0 + qrow + 8) * 36 + kk + qk + 4]);
            #pragma unroll
            for (int nt = 0; nt < 4; nt++) {
                uint32_t bb0 = __float_as_uint(smB[(b0 + nt * 8 + qrow) * 36 + kk + qk]);
                uint32_t bb1 = __float_as_uint(smB[(b0 + nt * 8 + qrow) * 36 + kk + qk + 4]);
                mma_tf32(c[nt][0], c[nt][1], c[nt][2], c[nt][3], a0, a1, a2, a3, bb0, bb1);
            }
        }
    }
    const int jg = jb * 64 + j0 + qrow;
    #pragma unroll
    for (int nt = 0; nt < 4; nt++) {
        const int bcol = b0 + nt * 8 + 2 * qk;
        g_part[(sp * BATCH + bcol)     * NJ + jg]     = c[nt][0];
        g_part[(sp * BATCH + bcol + 1) * NJ + jg]     = c[nt][1];
        g_part[(sp * BATCH + bcol)     * NJ + jg + 8] = c[nt][2];
        g_part[(sp * BATCH + bcol + 1) * NJ + jg + 8] = c[nt][3];
    }
}

// ---------------- K7: reduce split-K partials + fc1 bias ----------------
__global__ void k_redpart(const float* __restrict__ fc1b) {
    const int b = blockIdx.x, j = threadIdx.x;
    float y = fc1b[j];
    #pragma unroll
    for (int s = 0; s < NSPLIT; s++) y += g_part[(s * BATCH + b) * NJ + j];
    g_ybuf[b * NJ + j] = y;
}

// ---------------- K8: bn3 + leaky + fc2 + sigmoid ----------------
__global__ void k_final(const float* __restrict__ g3, const float* __restrict__ b3,
                        const float* __restrict__ w2, const float* __restrict__ bias2,
                        float* __restrict__ out) {
    __shared__ float sc[NJ], sh[NJ], w2s[NJ];
    const int t = threadIdx.x;
    float s = 0.f, ss = 0.f;
    for (int b = 0; b < BATCH; b++) {
        float v = g_ybuf[b * NJ + t];
        s += v; ss += v * v;
    }
    float m = s * (1.f / BATCH);
    float var = ss * (1.f / BATCH) - m * m;
    float scale = rsqrtf(var + EPSV) * g3[t];
    sc[t] = scale; sh[t] = b3[t] - m * scale; w2s[t] = w2[t];
    __syncthreads();
    const int warp = t / 32, lane = t % 32;
    for (int b = warp * 4; b < warp * 4 + 4; b++) {
        float p = 0.f;
        for (int j = lane; j < NJ; j += 32) {
            float v = g_ybuf[b * NJ + j] * sc[j] + sh[j];
            v = v > 0.f ? v : 0.2f * v;
            p += v * w2s[j];
        }
        #pragma unroll
        for (int off = 16; off > 0; off >>= 1)
            p += __shfl_down_sync(0xffffffffu, p, off);
        if (lane == 0) out[b] = 1.f / (1.f + expf(-(p + bias2[0])));
    }
}

// ---------------- launch ----------------
extern "C" void kernel_launch(void* const* d_in, const int* in_sizes, int n_in,
                              void* d_out, int out_size) {
    (void)in_sizes; (void)n_in; (void)out_size;
    const float* image = (const float*)d_in[0];
    const float* c1w = (const float*)d_in[1];
    const float* c1b = (const float*)d_in[2];
    const float* g1  = (const float*)d_in[3];
    const float* b1  = (const float*)d_in[4];
    const float* c2w = (const float*)d_in[5];
    const float* c2b = (const float*)d_in[6];
    const float* g2  = (const float*)d_in[7];
    const float* b2  = (const float*)d_in[8];
    const float* fw1 = (const float*)d_in[9];
    const float* fb1 = (const float*)d_in[10];
    const float* g3  = (const float*)d_in[11];
    const float* b3  = (const float*)d_in[12];
    const float* fw2 = (const float*)d_in[13];
    const float* fb2 = (const float*)d_in[14];
    float* out = (float*)d_out;

    cudaFuncSetAttribute(k_conv1_mma, cudaFuncAttributeMaxDynamicSharedMemorySize,
                         C1_SMEM_BYTES);
    cudaFuncSetAttribute(k_conv2_mma, cudaFuncAttributeMaxDynamicSharedMemorySize,
                         C2_SMEM_BYTES);

    k_layout    <<<dim3(4, 64), 256>>>(image, c2w);
    k_conv1_mma <<<dim3(13, 64), 256, C1_SMEM_BYTES>>>(c1w, c1b);
    k_red1b     <<<OC1, 256>>>();
    k_conv2_mma <<<dim3(8, 64, 2), 256, C2_SMEM_BYTES>>>(g1, b1);
    k_c2merge   <<<dim3(OC2, 8), 256>>>(c2b);
    k_fc1_mma   <<<dim3(8, NSPLIT), 256>>>(fw1, g2, b2);
    k_redpart   <<<BATCH, NJ>>>(fb1);
    k_final     <<<1, NJ>>>(g3, b3, fw2, fb2, out);
}